// round 16
// baseline (speedup 1.0000x reference)
#include <cuda_runtime.h>
#include <cuda_fp16.h>
#include <math.h>
#include <stdint.h>

// ---------------------------------------------------------------------------
// Problem constants
// ---------------------------------------------------------------------------
#define D_MODEL   512
#define D_STATE   128
#define HEADDIM   64
#define D_INNER   1024
#define NHEADS    16
#define CONV_DIM  1280
#define D_IN_PROJ 2320
#define LSEQ      64
#define NSEQ      128
#define NTOK      8192
#define EPS       1e-5f

#define NPAD_IN   2432
#define ZXSZ      ((size_t)NTOK * D_IN_PROJ)
#define XBCSZ     ((size_t)NTOK * CONV_DIM)
#define YSZ       ((size_t)NTOK * D_INNER)
#define GSZ       ((size_t)NSEQ * LSEQ * LSEQ)
#define ASZ       ((size_t)NTOK * 2 * D_INNER)
#define WINSZ     ((size_t)NPAD_IN * D_MODEL)
#define WOUTSZ    ((size_t)D_MODEL * D_INNER)

// ---------------------------------------------------------------------------
// Device scratch
// ---------------------------------------------------------------------------
__device__ float g_zx  [2 * ZXSZ];
__device__ float g_xbc [2 * XBCSZ];
__device__ float g_y   [2 * YSZ];
__device__ float g_G   [2 * GSZ];
__device__ __half g_xsplit [(size_t)NTOK * 2 * D_MODEL];
__device__ __half g_asplitA[2 * ASZ];
__device__ __half g_asplitB[ASZ];
__device__ __half g_win [2 * WINSZ];
__device__ __half g_wout[2 * WOUTSZ];
__device__ __half g_wfc [WOUTSZ];

// ---------------------------------------------------------------------------
// Helpers
// ---------------------------------------------------------------------------
__device__ __forceinline__ uint32_t smem_u32(const void* p) {
    uint32_t a;
    asm("{ .reg .u64 t; cvta.to.shared.u64 t, %1; cvt.u32.u64 %0, t; }"
        : "=r"(a) : "l"(p));
    return a;
}
#define SWZ128(o) ((o) ^ (((o) >> 3) & 0x70))
#define CP_ASYNC16(dst, src) \
    asm volatile("cp.async.cg.shared.global [%0], [%1], 16;" :: "r"(dst), "l"(src) : "memory")

__device__ __forceinline__ void ldmatrix_x4(uint32_t* r, uint32_t addr) {
    asm volatile("ldmatrix.sync.aligned.m8n8.x4.shared.b16 {%0,%1,%2,%3}, [%4];"
                 : "=r"(r[0]), "=r"(r[1]), "=r"(r[2]), "=r"(r[3]) : "r"(addr));
}
__device__ __forceinline__ void mma_f16(float* d, const uint32_t* a,
                                        uint32_t b0, uint32_t b1) {
    asm volatile(
        "mma.sync.aligned.m16n8k16.row.col.f32.f16.f16.f32 "
        "{%0,%1,%2,%3}, {%4,%5,%6,%7}, {%8,%9}, {%0,%1,%2,%3};"
        : "+f"(d[0]), "+f"(d[1]), "+f"(d[2]), "+f"(d[3])
        : "r"(a[0]), "r"(a[1]), "r"(a[2]), "r"(a[3]), "r"(b0), "r"(b1));
}
__device__ __forceinline__ void split2h(float a, __half& hi, __half& lo) {
    hi = __float2half_rn(a);
    lo = __float2half_rn(a - __half2float(hi));
}
__device__ __forceinline__ int swap66(int r) {
    return (r & ~0xFFF) | ((r & 63) << 6) | ((r >> 6) & 63);
}
__device__ __forceinline__ float fsilu(float v) {
    return __fdividef(v, 1.f + __expf(-v));
}

// ---------------------------------------------------------------------------
// mma.sync split-fp16 GEMM, hi/lo fused per k-chunk; batched over dirs via
// blockIdx.z. Warp layout 2(M) x 4(N), warp tile 64x32. 2-stage double buffer.
// Hoisted swizzle: SWZ128(row*128 + ks*32 + lcol) = row*128 + ((lcol^xorv)^ks32)
// with xorv = (lrow&7)<<4, since ks/lcol bits never reach the XOR source field.
// ---------------------------------------------------------------------------
#define GST       49152u
#define GSM_TOTAL (2 * 49152)

__device__ __forceinline__ void gemm_load_tile(
    const __half* __restrict__ A, const __half* __restrict__ W,
    uint32_t sb, int m0, int n0, int KW, int kt, int stage, int tid, int permA)
{
    uint32_t ah_dst = sb + stage * GST;
    uint32_t al_dst = ah_dst + 16384;
    uint32_t b_dst  = ah_dst + 32768;
    int ka = kt * 64;
    const int K2 = 2 * KW;
#pragma unroll
    for (int j = 0; j < 4; ++j) {
        int idx = tid + j * 256;
        int row = idx >> 3, c = idx & 7;
        uint32_t off = SWZ128((uint32_t)(row * 128 + c * 16));
        int ar = m0 + row;
        if (permA) ar = swap66(ar);
        const __half* ap = A + ((size_t)ar * K2 + ka + c * 8);
        CP_ASYNC16(ah_dst + off, ap);
        CP_ASYNC16(al_dst + off, ap + KW);
        CP_ASYNC16(b_dst + off, W + ((size_t)(n0 + row) * KW + ka + c * 8));
    }
}

__global__ __launch_bounds__(256, 2)
void gemm_tc_kernel(const __half* __restrict__ A, size_t aStride,
                    const __half* __restrict__ W0, const __half* __restrict__ W1,
                    float* __restrict__ C, size_t cStride,
                    __half* __restrict__ dsplit,
                    int KW, int N, int ldc, int col0a, int col0b,
                    const float* __restrict__ bias, int permAz, int permCz)
{
    extern __shared__ char smem[];
    uint32_t sb = smem_u32(smem);
    const int tid  = threadIdx.x;
    const int wid  = tid >> 5;
    const int lane = tid & 31;
    const int wm   = wid & 1;
    const int wn   = wid >> 1;
    const int m0   = blockIdx.y * 128;
    const int n0   = blockIdx.x * 128;
    const int z    = blockIdx.z;

    const __half* W = z ? W1 : W0;
    const __half* Az = A + (size_t)z * aStride;
    float* Cz = C ? (C + (size_t)z * cStride) : C;
    const int permA = permAz && z;
    const int permC = permCz && z;
    const int col0  = z ? col0b : col0a;

    float acc[4][4][4];
#pragma unroll
    for (int i = 0; i < 4; ++i)
#pragma unroll
        for (int j = 0; j < 4; ++j) {
            acc[i][j][0] = 0.f; acc[i][j][1] = 0.f;
            acc[i][j][2] = 0.f; acc[i][j][3] = 0.f;
        }

    const int nK = KW / 64;
    gemm_load_tile(Az, W, sb, m0, n0, KW, 0, 0, tid, permA);
    asm volatile("cp.async.commit_group;" ::: "memory");

    const int lrow = lane & 15;
    const int lcol = (lane >> 4) * 16;
    const uint32_t kc = ((uint32_t)lcol) ^ ((uint32_t)((lrow & 7) << 4));
    uint32_t pA[4], pB[2];
#pragma unroll
    for (int im = 0; im < 4; ++im)
        pA[im] = (uint32_t)((wm * 64 + im * 16 + lrow) * 128) + kc;
#pragma unroll
    for (int in2 = 0; in2 < 2; ++in2)
        pB[in2] = (uint32_t)((wn * 32 + in2 * 16 + lrow) * 128) + kc;

    for (int i = 0; i < nK; ++i) {
        if (i + 1 < nK) {
            gemm_load_tile(Az, W, sb, m0, n0, KW, i + 1, (i + 1) & 1, tid, permA);
            asm volatile("cp.async.commit_group;" ::: "memory");
            asm volatile("cp.async.wait_group 1;" ::: "memory");
        } else {
            asm volatile("cp.async.wait_group 0;" ::: "memory");
        }
        __syncthreads();

        uint32_t ahBase = sb + (i & 1) * GST;
        uint32_t alBase = ahBase + 16384;
        uint32_t bBase  = ahBase + 32768;
#pragma unroll
        for (int ks = 0; ks < 4; ++ks) {
            const uint32_t kx = (uint32_t)(ks * 32);
            uint32_t bf[2][4];
#pragma unroll
            for (int in2 = 0; in2 < 2; ++in2)
                ldmatrix_x4(bf[in2], bBase + (pB[in2] ^ kx));
            uint32_t af[4][4];
            // hi set
#pragma unroll
            for (int im = 0; im < 4; ++im)
                ldmatrix_x4(af[im], ahBase + (pA[im] ^ kx));
#pragma unroll
            for (int im = 0; im < 4; ++im)
#pragma unroll
                for (int in = 0; in < 4; ++in) {
                    uint32_t b0 = bf[in >> 1][in & 1];
                    uint32_t b1 = bf[in >> 1][2 + (in & 1)];
                    mma_f16(acc[im][in], af[im], b0, b1);
                }
            // lo set (reuse af registers)
#pragma unroll
            for (int im = 0; im < 4; ++im)
                ldmatrix_x4(af[im], alBase + (pA[im] ^ kx));
#pragma unroll
            for (int im = 0; im < 4; ++im)
#pragma unroll
                for (int in = 0; in < 4; ++in) {
                    uint32_t b0 = bf[in >> 1][in & 1];
                    uint32_t b1 = bf[in >> 1][2 + (in & 1)];
                    mma_f16(acc[im][in], af[im], b0, b1);
                }
        }
        __syncthreads();
    }

    // epilogue
#pragma unroll
    for (int im = 0; im < 4; ++im) {
        int m  = m0 + wm * 64 + im * 16 + (lane >> 2);
        int r0 = permC ? swap66(m)     : m;
        int r1 = permC ? swap66(m + 8) : (m + 8);
#pragma unroll
        for (int in = 0; in < 4; ++in) {
            int n = n0 + wn * 32 + in * 8 + (lane & 3) * 2;
            if (n >= N) continue;
            float2 v0 = make_float2(acc[im][in][0], acc[im][in][1]);
            float2 v1 = make_float2(acc[im][in][2], acc[im][in][3]);
            if (dsplit) {
                __half h0, l0, h1, l1;
                split2h(v0.x, h0, l0); split2h(v0.y, h1, l1);
                *(__half2*)(dsplit + (size_t)r0 * 2048 + col0 + n) =
                    __halves2half2(h0, h1);
                *(__half2*)(dsplit + (size_t)r0 * 2048 + 1024 + col0 + n) =
                    __halves2half2(l0, l1);
                split2h(v1.x, h0, l0); split2h(v1.y, h1, l1);
                *(__half2*)(dsplit + (size_t)r1 * 2048 + col0 + n) =
                    __halves2half2(h0, h1);
                *(__half2*)(dsplit + (size_t)r1 * 2048 + 1024 + col0 + n) =
                    __halves2half2(l0, l1);
            } else {
                if (bias) {
                    float b0 = bias[n], b1 = bias[n + 1];
                    v0.x += b0; v0.y += b1;
                    v1.x += b0; v1.y += b1;
                }
                *(float2*)(Cz + (size_t)r0 * ldc + col0 + n) = v0;
                *(float2*)(Cz + (size_t)r1 * ldc + col0 + n) = v1;
            }
        }
    }
}

// ---------------------------------------------------------------------------
// Activation split (x -> hi|lo fp16)
// ---------------------------------------------------------------------------
__global__ void split_act_h_kernel(const float* __restrict__ A, __half* __restrict__ out)
{
    size_t idx = (size_t)blockIdx.x * blockDim.x + threadIdx.x;
    if (idx >= (size_t)NTOK * 256) return;
    int m = (int)(idx >> 8), kp = (int)(idx & 255);
    float2 a = *(const float2*)(A + ((size_t)m << 9) + kp * 2);
    __half h0, l0, h1, l1;
    split2h(a.x, h0, l0); split2h(a.y, h1, l1);
    size_t base = (size_t)m * 1024 + kp * 2;
    *(__half2*)(out + base)       = __halves2half2(h0, h1);
    *(__half2*)(out + base + 512) = __halves2half2(l0, l1);
}

// ---------------------------------------------------------------------------
// Unified weight prep: grid.y segments
//  0/1: in_w h/v  (K=512,  N=D_IN_PROJ pad NPAD_IN) -> win
//  2/3: out_w h/v (K=1024, N=512)                   -> wout
//  4:   fc effective (pre-summed) fp16              -> wfc
// ---------------------------------------------------------------------------
__global__ void prep_w_kernel(const float* __restrict__ hin, const float* __restrict__ vin,
                              const float* __restrict__ hout, const float* __restrict__ vout,
                              const float* __restrict__ fcw,
                              __half* __restrict__ win, __half* __restrict__ wout,
                              __half* __restrict__ wfc)
{
    const int seg = blockIdx.y;
    size_t idx = (size_t)blockIdx.x * blockDim.x + threadIdx.x;
    if (seg < 2) {
        if (idx >= ((size_t)NPAD_IN * 512) >> 1) return;
        const float* W = seg ? vin : hin;
        __half* o = win + (size_t)seg * WINSZ;
        int n = (int)(idx >> 8), kp = (int)(idx & 255);
        float2 w = (n < D_IN_PROJ) ? *(const float2*)(W + (size_t)n * 512 + kp * 2)
                                   : make_float2(0.f, 0.f);
        *(__half2*)(o + (size_t)n * 512 + kp * 2) =
            __halves2half2(__float2half_rn(w.x), __float2half_rn(w.y));
    } else if (seg < 4) {
        if (idx >= ((size_t)512 * 1024) >> 1) return;
        const float* W = (seg == 3) ? vout : hout;
        __half* o = wout + (size_t)(seg - 2) * WOUTSZ;
        int n = (int)(idx >> 9), kp = (int)(idx & 511);
        float2 w = *(const float2*)(W + (size_t)n * 1024 + kp * 2);
        *(__half2*)(o + (size_t)n * 1024 + kp * 2) =
            __halves2half2(__float2half_rn(w.x), __float2half_rn(w.y));
    } else {
        if (idx >= (size_t)(D_MODEL * D_INNER) >> 1) return;
        int o = (int)(idx >> 9);
        int j = (int)(idx & 511) * 2;
        float v0, v1;
        if (j < 512) {
            v0 = fcw[(size_t)o * 2048 + j]     + fcw[(size_t)o * 2048 + 512 + j];
            v1 = fcw[(size_t)o * 2048 + j + 1] + fcw[(size_t)o * 2048 + 512 + j + 1];
        } else {
            int jj = j - 512;
            v0 = fcw[(size_t)o * 2048 + 1024 + jj]     + fcw[(size_t)o * 2048 + 1536 + jj];
            v1 = fcw[(size_t)o * 2048 + 1024 + jj + 1] + fcw[(size_t)o * 2048 + 1536 + jj + 1];
        }
        *(__half2*)(wfc + (size_t)o * 1024 + j) =
            __halves2half2(__float2half_rn(v0), __float2half_rn(v1));
    }
}

// ---------------------------------------------------------------------------
// Depthwise causal conv (width 4) + SiLU; batched over dirs
// ---------------------------------------------------------------------------
#define C4N (CONV_DIM / 4)
__global__ void conv_silu_kernel(const float* __restrict__ zxAll,
                                 const float* __restrict__ cw0, const float* __restrict__ cw1,
                                 const float* __restrict__ cb0, const float* __restrict__ cb1,
                                 float* __restrict__ xbcAll)
{
    int idx = blockIdx.x * blockDim.x + threadIdx.x;
    if (idx >= NSEQ * 4 * C4N) return;
    const int z = blockIdx.y;
    const float* zx  = zxAll + (size_t)z * ZXSZ;
    const float* cw  = z ? cw1 : cw0;
    const float* cb  = z ? cb1 : cb0;
    float* xbc = xbcAll + (size_t)z * XBCSZ;

    int c4  = idx % C4N;
    int tmp = idx / C4N;
    int tc  = tmp & 3;
    int seq = tmp >> 2;
    int c   = c4 * 4;
    int t0  = tc * 16;

    float4 w[4];
#pragma unroll
    for (int j = 0; j < 4; ++j) w[j] = *(const float4*)(cw + (c + j) * 4);
    float4 b = *(const float4*)(cb + c);

    size_t ibase = (size_t)seq * LSEQ * D_IN_PROJ + D_INNER + c;
    size_t obase = (size_t)seq * LSEQ * CONV_DIM + c;

    float4 zero = make_float4(0.f, 0.f, 0.f, 0.f);
    float4 x0, x1, x2;
    if (t0 == 0) { x0 = zero; x1 = zero; x2 = zero; }
    else {
        x0 = *(const float4*)(zx + ibase + (size_t)(t0 - 3) * D_IN_PROJ);
        x1 = *(const float4*)(zx + ibase + (size_t)(t0 - 2) * D_IN_PROJ);
        x2 = *(const float4*)(zx + ibase + (size_t)(t0 - 1) * D_IN_PROJ);
    }
#pragma unroll
    for (int t = 0; t < 16; ++t) {
        float4 xt = *(const float4*)(zx + ibase + (size_t)(t0 + t) * D_IN_PROJ);
        float4 v;
        v.x = fmaf(x0.x, w[0].x, fmaf(x1.x, w[0].y, fmaf(x2.x, w[0].z, fmaf(xt.x, w[0].w, b.x))));
        v.y = fmaf(x0.y, w[1].x, fmaf(x1.y, w[1].y, fmaf(x2.y, w[1].z, fmaf(xt.y, w[1].w, b.y))));
        v.z = fmaf(x0.z, w[2].x, fmaf(x1.z, w[2].y, fmaf(x2.z, w[2].z, fmaf(xt.z, w[2].w, b.z))));
        v.w = fmaf(x0.w, w[3].x, fmaf(x1.w, w[3].y, fmaf(x2.w, w[3].z, fmaf(xt.w, w[3].w, b.w))));
        v.x = fsilu(v.x);
        v.y = fsilu(v.y);
        v.z = fsilu(v.z);
        v.w = fsilu(v.w);
        *(float4*)(xbc + obase + (size_t)(t0 + t) * CONV_DIM) = v;
        x0 = x1; x1 = x2; x2 = xt;
    }
}

// ---------------------------------------------------------------------------
// G kernel: block per (seq, dir). G[t][s] = C[t].B[s]
// ---------------------------------------------------------------------------
#define GK_BCS 132
#define GK_BTS 68
#define GK_SMEM ((64 * GK_BCS + 128 * GK_BTS) * 4)

__global__ __launch_bounds__(256)
void gmat_kernel(const float* __restrict__ xbcAll, float* __restrict__ GAll)
{
    extern __shared__ float sm[];
    float* Cs = sm;
    float* Bt = Cs + 64 * GK_BCS;

    const int seq = blockIdx.x;
    const int z   = blockIdx.y;
    const int tid = threadIdx.x;
    const float* xbc = xbcAll + (size_t)z * XBCSZ;

    for (int i = tid; i < 64 * 128; i += 256) {
        int t = i >> 7, n = i & 127;
        size_t base = (size_t)(seq * LSEQ + t) * CONV_DIM;
        Bt[n * GK_BTS + t] = xbc[base + D_INNER + n];
        Cs[t * GK_BCS + n] = xbc[base + D_INNER + D_STATE + n];
    }
    __syncthreads();

    const int tt = (tid >> 4) << 2;
    const int ss = (tid & 15) << 2;

    float wa[4][4];
#pragma unroll
    for (int i = 0; i < 4; ++i)
#pragma unroll
        for (int j = 0; j < 4; ++j) wa[i][j] = 0.f;

    if (ss <= tt + 3) {
        for (int n = 0; n < 128; n += 4) {
            float4 cr[4], bt[4];
#pragma unroll
            for (int i = 0; i < 4; ++i) cr[i] = *(const float4*)&Cs[(tt + i) * GK_BCS + n];
#pragma unroll
            for (int k = 0; k < 4; ++k) bt[k] = *(const float4*)&Bt[(n + k) * GK_BTS + ss];
#pragma unroll
            for (int i = 0; i < 4; ++i) {
                wa[i][0] = fmaf(cr[i].x, bt[0].x, wa[i][0]);
                wa[i][1] = fmaf(cr[i].x, bt[0].y, wa[i][1]);
                wa[i][2] = fmaf(cr[i].x, bt[0].z, wa[i][2]);
                wa[i][3] = fmaf(cr[i].x, bt[0].w, wa[i][3]);
                wa[i][0] = fmaf(cr[i].y, bt[1].x, wa[i][0]);
                wa[i][1] = fmaf(cr[i].y, bt[1].y, wa[i][1]);
                wa[i][2] = fmaf(cr[i].y, bt[1].z, wa[i][2]);
                wa[i][3] = fmaf(cr[i].y, bt[1].w, wa[i][3]);
                wa[i][0] = fmaf(cr[i].z, bt[2].x, wa[i][0]);
                wa[i][1] = fmaf(cr[i].z, bt[2].y, wa[i][1]);
                wa[i][2] = fmaf(cr[i].z, bt[2].z, wa[i][2]);
                wa[i][3] = fmaf(cr[i].z, bt[2].w, wa[i][3]);
                wa[i][0] = fmaf(cr[i].w, bt[3].x, wa[i][0]);
                wa[i][1] = fmaf(cr[i].w, bt[3].y, wa[i][1]);
                wa[i][2] = fmaf(cr[i].w, bt[3].z, wa[i][2]);
                wa[i][3] = fmaf(cr[i].w, bt[3].w, wa[i][3]);
            }
        }
    }
    float* gp = GAll + (size_t)z * GSZ + (size_t)seq * 4096;
#pragma unroll
    for (int i = 0; i < 4; ++i)
        *(float4*)&gp[(tt + i) * 64 + ss] =
            make_float4(wa[i][0], wa[i][1], wa[i][2], wa[i][3]);
}

// ---------------------------------------------------------------------------
// SSM phase-2: block per (seq*head, dir). Balanced row-pair assignment.
// ---------------------------------------------------------------------------
#define S2S 68

__global__ __launch_bounds__(256)
void ssm2_kernel(const float* __restrict__ zxAll, const float* __restrict__ xbcAll,
                 const float* __restrict__ GAll,
                 const float* __restrict__ A0, const float* __restrict__ A1,
                 const float* __restrict__ db0, const float* __restrict__ db1,
                 const float* __restrict__ Dp0, const float* __restrict__ Dp1,
                 float* __restrict__ yAll)
{
    __shared__ float Wts[64 * S2S];
    __shared__ float xs [64 * S2S];
    __shared__ float dts[64];
    __shared__ float css[64];

    const int z   = blockIdx.y;
    const int seq = blockIdx.x >> 4;
    const int h   = blockIdx.x & 15;
    const int tid = threadIdx.x;

    const float* zx  = zxAll  + (size_t)z * ZXSZ;
    const float* xbc = xbcAll + (size_t)z * XBCSZ;
    const float* G   = GAll   + (size_t)z * GSZ;
    const float* A_log   = z ? A1  : A0;
    const float* dt_bias = z ? db1 : db0;
    const float* Dp      = z ? Dp1 : Dp0;
    float* y = yAll + (size_t)z * YSZ;

    for (int i = tid; i < 64 * 64; i += 256) {
        int t = i >> 6, p = i & 63;
        xs[t * S2S + p] = xbc[(size_t)(seq * LSEQ + t) * CONV_DIM + h * HEADDIM + p];
    }
    if (tid < 64) {
        float raw = zx[(size_t)(seq * LSEQ + tid) * D_IN_PROJ + (D_INNER + CONV_DIM) + h]
                    + dt_bias[h];
        dts[tid] = (raw > 20.f) ? raw : log1pf(__expf(raw));
    }
    __syncthreads();
    if (tid == 0) {
        float a = -__expf(A_log[h]);
        float run = 0.f;
        for (int t = 0; t < 64; ++t) { run += dts[t] * a; css[t] = run; }
    }
    __syncthreads();

    const float* gp = G + (size_t)seq * 4096;
    for (int i = tid; i < 1024; i += 256) {
        int t  = i >> 4;
        int s4 = (i & 15) << 2;
        float4 g = *(const float4*)&gp[t * 64 + s4];
        float4 wv;
        wv.x = (s4 + 0 <= t) ? g.x * __expf(css[t] - css[s4 + 0]) * dts[s4 + 0] : 0.f;
        wv.y = (s4 + 1 <= t) ? g.y * __expf(css[t] - css[s4 + 1]) * dts[s4 + 1] : 0.f;
        wv.z = (s4 + 2 <= t) ? g.z * __expf(css[t] - css[s4 + 2]) * dts[s4 + 2] : 0.f;
        wv.w = (s4 + 3 <= t) ? g.w * __expf(css[t] - css[s4 + 3]) * dts[s4 + 3] : 0.f;
        *(float4*)&Wts[t * S2S + s4] = wv;
    }
    __syncthreads();

    const int tb = tid >> 4;
    const int ss = (tid & 15) << 2;
    const float dcoef = Dp[h];

#pragma unroll
    for (int pr = 0; pr < 2; ++pr) {
        const int r0 = pr ? (62 - 2 * tb) : (2 * tb);
        const int hiB = r0 + 1;
        float ya[2][4];
#pragma unroll
        for (int i = 0; i < 2; ++i) {
            float4 xv = *(const float4*)&xs[(r0 + i) * S2S + ss];
            ya[i][0] = dcoef * xv.x; ya[i][1] = dcoef * xv.y;
            ya[i][2] = dcoef * xv.z; ya[i][3] = dcoef * xv.w;
        }
        for (int s0 = 0; s0 <= hiB; s0 += 4) {
            float4 wr[2], xr[4];
#pragma unroll
            for (int i = 0; i < 2; ++i) wr[i] = *(const float4*)&Wts[(r0 + i) * S2S + s0];
#pragma unroll
            for (int k = 0; k < 4; ++k) xr[k] = *(const float4*)&xs[(s0 + k) * S2S + ss];
#pragma unroll
            for (int i = 0; i < 2; ++i) {
                ya[i][0] = fmaf(wr[i].x, xr[0].x, ya[i][0]);
                ya[i][1] = fmaf(wr[i].x, xr[0].y, ya[i][1]);
                ya[i][2] = fmaf(wr[i].x, xr[0].z, ya[i][2]);
                ya[i][3] = fmaf(wr[i].x, xr[0].w, ya[i][3]);
                ya[i][0] = fmaf(wr[i].y, xr[1].x, ya[i][0]);
                ya[i][1] = fmaf(wr[i].y, xr[1].y, ya[i][1]);
                ya[i][2] = fmaf(wr[i].y, xr[1].z, ya[i][2]);
                ya[i][3] = fmaf(wr[i].y, xr[1].w, ya[i][3]);
                ya[i][0] = fmaf(wr[i].z, xr[2].x, ya[i][0]);
                ya[i][1] = fmaf(wr[i].z, xr[2].y, ya[i][1]);
                ya[i][2] = fmaf(wr[i].z, xr[2].z, ya[i][2]);
                ya[i][3] = fmaf(wr[i].z, xr[2].w, ya[i][3]);
                ya[i][0] = fmaf(wr[i].w, xr[3].x, ya[i][0]);
                ya[i][1] = fmaf(wr[i].w, xr[3].y, ya[i][1]);
                ya[i][2] = fmaf(wr[i].w, xr[3].z, ya[i][2]);
                ya[i][3] = fmaf(wr[i].w, xr[3].w, ya[i][3]);
            }
        }
#pragma unroll
        for (int i = 0; i < 2; ++i) {
            float4 v = make_float4(ya[i][0], ya[i][1], ya[i][2], ya[i][3]);
            *(float4*)&y[(size_t)(seq * LSEQ + r0 + i) * D_INNER + h * HEADDIM + ss] = v;
        }
    }
}

// ---------------------------------------------------------------------------
// Gated RMSNorm + fp16 split emit; batched over dirs. Vectorized float4/half2.
// ---------------------------------------------------------------------------
__global__ __launch_bounds__(256)
void gate_norm_split_kernel(const float* __restrict__ zxAll,
                            const float* __restrict__ nw0, const float* __restrict__ nw1,
                            const float* __restrict__ yAll, __half* __restrict__ outAll)
{
    const int row = blockIdx.x;
    const int z   = blockIdx.y;
    const int tid = threadIdx.x;
    __shared__ float wsum[8];

    const float* zx = zxAll + (size_t)z * ZXSZ;
    const float* y  = yAll  + (size_t)z * YSZ;
    const float* norm_w = z ? nw1 : nw0;
    __half* out = outAll + (size_t)z * ASZ;

    const int c = tid * 4;
    float4 zz = *(const float4*)(zx + (size_t)row * D_IN_PROJ + c);
    float4 yv = *(const float4*)(y  + (size_t)row * D_INNER   + c);
    float4 g;
    g.x = yv.x * fsilu(zz.x);
    g.y = yv.y * fsilu(zz.y);
    g.z = yv.z * fsilu(zz.z);
    g.w = yv.w * fsilu(zz.w);
    float ss = g.x * g.x + g.y * g.y + g.z * g.z + g.w * g.w;
#pragma unroll
    for (int off = 16; off; off >>= 1)
        ss += __shfl_xor_sync(0xffffffffu, ss, off);
    if ((tid & 31) == 0) wsum[tid >> 5] = ss;
    __syncthreads();
    float tot = wsum[0] + wsum[1] + wsum[2] + wsum[3]
              + wsum[4] + wsum[5] + wsum[6] + wsum[7];
    float scale = rsqrtf(tot / (float)D_INNER + EPS);

    float4 nw = *(const float4*)(norm_w + c);
    float o0 = g.x * scale * nw.x;
    float o1 = g.y * scale * nw.y;
    float o2 = g.z * scale * nw.z;
    float o3 = g.w * scale * nw.w;
    __half h0, l0, h1, l1, h2, l2, h3, l3;
    split2h(o0, h0, l0); split2h(o1, h1, l1);
    split2h(o2, h2, l2); split2h(o3, h3, l3);
    size_t base = (size_t)row * 2048 + c;
    *(__half2*)(out + base)            = __halves2half2(h0, h1);
    *(__half2*)(out + base + 2)        = __halves2half2(h2, h3);
    *(__half2*)(out + base + 1024)     = __halves2half2(l0, l1);
    *(__half2*)(out + base + 1024 + 2) = __halves2half2(l2, l3);
}

// ---------------------------------------------------------------------------
// Host side
// ---------------------------------------------------------------------------
extern "C" void kernel_launch(void* const* d_in, const int* in_sizes, int n_in,
                              void* d_out, int out_size)
{
    (void)in_sizes; (void)n_in; (void)out_size;
    const float* x        = (const float*)d_in[0];
    const float* h_in_w   = (const float*)d_in[1];
    const float* h_conv_w = (const float*)d_in[2];
    const float* h_conv_b = (const float*)d_in[3];
    const float* h_A_log  = (const float*)d_in[4];
    const float* h_dt_b   = (const float*)d_in[5];
    const float* h_D      = (const float*)d_in[6];
    const float* h_norm_w = (const float*)d_in[7];
    const float* h_out_w  = (const float*)d_in[8];
    const float* v_in_w   = (const float*)d_in[9];
    const float* v_conv_w = (const float*)d_in[10];
    const float* v_conv_b = (const float*)d_in[11];
    const float* v_A_log  = (const float*)d_in[12];
    const float* v_dt_b   = (const float*)d_in[13];
    const float* v_D      = (const float*)d_in[14];
    const float* v_norm_w = (const float*)d_in[15];
    const float* v_out_w  = (const float*)d_in[16];
    const float* fc_w     = (const float*)d_in[17];
    const float* fc_b     = (const float*)d_in[18];
    float* out = (float*)d_out;

    float *zx, *xbc, *y, *G;
    __half *xsplit, *asplitA, *asplitB, *win, *wout, *wfc;
    cudaGetSymbolAddress((void**)&zx,      g_zx);
    cudaGetSymbolAddress((void**)&xbc,     g_xbc);
    cudaGetSymbolAddress((void**)&y,       g_y);
    cudaGetSymbolAddress((void**)&G,       g_G);
    cudaGetSymbolAddress((void**)&xsplit,  g_xsplit);
    cudaGetSymbolAddress((void**)&asplitA, g_asplitA);
    cudaGetSymbolAddress((void**)&asplitB, g_asplitB);
    cudaGetSymbolAddress((void**)&win,     g_win);
    cudaGetSymbolAddress((void**)&wout,    g_wout);
    cudaGetSymbolAddress((void**)&wfc,     g_wfc);

    cudaFuncSetAttribute(gmat_kernel, cudaFuncAttributeMaxDynamicSharedMemorySize,
                         GK_SMEM);
    cudaFuncSetAttribute(gemm_tc_kernel, cudaFuncAttributeMaxDynamicSharedMemorySize,
                         GSM_TOTAL);

    const int TPB = 256;

    // weight prep: one launch (5 segments), activation split: one launch
    {
        dim3 g((((size_t)NPAD_IN * 512 / 2) + TPB - 1) / TPB, 5);
        prep_w_kernel<<<g, TPB>>>(h_in_w, v_in_w, h_out_w, v_out_w, fc_w,
                                  win, wout, wfc);
    }
    split_act_h_kernel<<<(NTOK * 256 + TPB - 1) / TPB, TPB>>>(x, xsplit);

    // in-proj (both dirs)
    {
        dim3 g(NPAD_IN / 128, NTOK / 128, 2);
        gemm_tc_kernel<<<g, 256, GSM_TOTAL>>>(xsplit, 0, win, win + WINSZ,
                                              zx, ZXSZ, nullptr,
                                              512, D_IN_PROJ, D_IN_PROJ, 0, 0,
                                              nullptr, 1, 0);
    }
    {
        dim3 g((NSEQ * 4 * C4N + TPB - 1) / TPB, 2);
        conv_silu_kernel<<<g, TPB>>>(zx, h_conv_w, v_conv_w, h_conv_b, v_conv_b, xbc);
    }
    {
        dim3 g(NSEQ, 2);
        gmat_kernel<<<g, 256, GK_SMEM>>>(xbc, G);
    }
    {
        dim3 g(NSEQ * NHEADS, 2);
        ssm2_kernel<<<g, 256>>>(zx, xbc, G, h_A_log, v_A_log,
                                h_dt_b, v_dt_b, h_D, v_D, y);
    }
    {
        dim3 g(NTOK, 2);
        gate_norm_split_kernel<<<g, 256>>>(zx, h_norm_w, v_norm_w, y, asplitA);
    }
    // out-proj (both dirs)
    {
        dim3 g(512 / 128, NTOK / 128, 2);
        gemm_tc_kernel<<<g, 256, GSM_TOTAL>>>(asplitA, ASZ, wout, wout + WOUTSZ,
                                              nullptr, 0, asplitB,
                                              1024, 512, 0, 512, 0,
                                              nullptr, 0, 1);
    }
    // final fc
    {
        dim3 g(512 / 128, NTOK / 128, 1);
        gemm_tc_kernel<<<g, 256, GSM_TOTAL>>>(asplitB, 0, wfc, nullptr,
                                              out, 0, nullptr,
                                              1024, 512, 512, 0, 0, fc_b, 0, 0);
    }
}

// round 17
// speedup vs baseline: 1.5389x; 1.5389x over previous
#include <cuda_runtime.h>
#include <cuda_fp16.h>
#include <math.h>
#include <stdint.h>

// ---------------------------------------------------------------------------
// Problem constants
// ---------------------------------------------------------------------------
#define D_MODEL   512
#define D_STATE   128
#define HEADDIM   64
#define D_INNER   1024
#define NHEADS    16
#define CONV_DIM  1280
#define D_IN_PROJ 2320
#define LSEQ      64
#define NSEQ      128
#define NTOK      8192
#define EPS       1e-5f

#define NPAD_IN   2432
#define ZXSZ      ((size_t)NTOK * D_IN_PROJ)
#define XBCSZ     ((size_t)NTOK * CONV_DIM)
#define YSZ       ((size_t)NTOK * D_INNER)
#define GSZ       ((size_t)NSEQ * LSEQ * LSEQ)
#define ASZ       ((size_t)NTOK * 2 * D_INNER)
#define WINSZ     ((size_t)NPAD_IN * D_MODEL)
#define WOUTSZ    ((size_t)D_MODEL * D_INNER)

// ---------------------------------------------------------------------------
// Device scratch
// ---------------------------------------------------------------------------
__device__ float g_zx  [2 * ZXSZ];
__device__ float g_xbc [2 * XBCSZ];
__device__ float g_y   [2 * YSZ];
__device__ float g_G   [2 * GSZ];
__device__ __half g_xsplit [(size_t)NTOK * 2 * D_MODEL];
__device__ __half g_asplitA[2 * ASZ];
__device__ __half g_asplitB[ASZ];
__device__ __half g_win [2 * WINSZ];
__device__ __half g_wout[2 * WOUTSZ];
__device__ __half g_wfc [WOUTSZ];

// ---------------------------------------------------------------------------
// Helpers
// ---------------------------------------------------------------------------
__device__ __forceinline__ uint32_t smem_u32(const void* p) {
    uint32_t a;
    asm("{ .reg .u64 t; cvta.to.shared.u64 t, %1; cvt.u32.u64 %0, t; }"
        : "=r"(a) : "l"(p));
    return a;
}
#define SWZ128(o) ((o) ^ (((o) >> 3) & 0x70))
#define CP_ASYNC16(dst, src) \
    asm volatile("cp.async.cg.shared.global [%0], [%1], 16;" :: "r"(dst), "l"(src) : "memory")

__device__ __forceinline__ void ldmatrix_x4(uint32_t* r, uint32_t addr) {
    asm volatile("ldmatrix.sync.aligned.m8n8.x4.shared.b16 {%0,%1,%2,%3}, [%4];"
                 : "=r"(r[0]), "=r"(r[1]), "=r"(r[2]), "=r"(r[3]) : "r"(addr));
}
__device__ __forceinline__ void mma_f16(float* d, const uint32_t* a,
                                        uint32_t b0, uint32_t b1) {
    asm volatile(
        "mma.sync.aligned.m16n8k16.row.col.f32.f16.f16.f32 "
        "{%0,%1,%2,%3}, {%4,%5,%6,%7}, {%8,%9}, {%0,%1,%2,%3};"
        : "+f"(d[0]), "+f"(d[1]), "+f"(d[2]), "+f"(d[3])
        : "r"(a[0]), "r"(a[1]), "r"(a[2]), "r"(a[3]), "r"(b0), "r"(b1));
}
__device__ __forceinline__ void split2h(float a, __half& hi, __half& lo) {
    hi = __float2half_rn(a);
    lo = __float2half_rn(a - __half2float(hi));
}
__device__ __forceinline__ int swap66(int r) {
    return (r & ~0xFFF) | ((r & 63) << 6) | ((r >> 6) & 63);
}
__device__ __forceinline__ float fsilu(float v) {
    return __fdividef(v, 1.f + __expf(-v));
}

// ---------------------------------------------------------------------------
// mma.sync split-fp16 GEMM, hi/lo fused per k-chunk; batched over dirs via
// blockIdx.z. Warp layout 2(M) x 4(N), warp tile 64x32. 2-stage double buffer.
// (round-15 proven configuration — mainloop frozen)
// ---------------------------------------------------------------------------
#define GST       49152u
#define GSM_TOTAL (2 * 49152)

__device__ __forceinline__ void gemm_load_tile(
    const __half* __restrict__ A, const __half* __restrict__ W,
    uint32_t sb, int m0, int n0, int KW, int kt, int stage, int tid, int permA)
{
    uint32_t ah_dst = sb + stage * GST;
    uint32_t al_dst = ah_dst + 16384;
    uint32_t b_dst  = ah_dst + 32768;
    int ka = kt * 64;
    const int K2 = 2 * KW;
#pragma unroll
    for (int j = 0; j < 4; ++j) {
        int idx = tid + j * 256;
        int row = idx >> 3, c = idx & 7;
        uint32_t off = SWZ128((uint32_t)(row * 128 + c * 16));
        int ar = m0 + row;
        if (permA) ar = swap66(ar);
        const __half* ap = A + ((size_t)ar * K2 + ka + c * 8);
        CP_ASYNC16(ah_dst + off, ap);
        CP_ASYNC16(al_dst + off, ap + KW);
        CP_ASYNC16(b_dst + off, W + ((size_t)(n0 + row) * KW + ka + c * 8));
    }
}

__global__ __launch_bounds__(256)
void gemm_tc_kernel(const __half* __restrict__ A, size_t aStride,
                    const __half* __restrict__ W0, const __half* __restrict__ W1,
                    float* __restrict__ C, size_t cStride,
                    __half* __restrict__ dsplit,
                    int KW, int N, int ldc, int col0a, int col0b,
                    const float* __restrict__ bias, int permAz, int permCz)
{
    extern __shared__ char smem[];
    uint32_t sb = smem_u32(smem);
    const int tid  = threadIdx.x;
    const int wid  = tid >> 5;
    const int lane = tid & 31;
    const int wm   = wid & 1;
    const int wn   = wid >> 1;
    const int m0   = blockIdx.y * 128;
    const int n0   = blockIdx.x * 128;
    const int z    = blockIdx.z;

    const __half* W = z ? W1 : W0;
    const __half* Az = A + (size_t)z * aStride;
    float* Cz = C ? (C + (size_t)z * cStride) : C;
    const int permA = permAz && z;
    const int permC = permCz && z;
    const int col0  = z ? col0b : col0a;

    float acc[4][4][4];
#pragma unroll
    for (int i = 0; i < 4; ++i)
#pragma unroll
        for (int j = 0; j < 4; ++j) {
            acc[i][j][0] = 0.f; acc[i][j][1] = 0.f;
            acc[i][j][2] = 0.f; acc[i][j][3] = 0.f;
        }

    const int nK = KW / 64;
    gemm_load_tile(Az, W, sb, m0, n0, KW, 0, 0, tid, permA);
    asm volatile("cp.async.commit_group;" ::: "memory");

    const int lrow = lane & 15;
    const int lcol = (lane >> 4) * 16;

    for (int i = 0; i < nK; ++i) {
        if (i + 1 < nK) {
            gemm_load_tile(Az, W, sb, m0, n0, KW, i + 1, (i + 1) & 1, tid, permA);
            asm volatile("cp.async.commit_group;" ::: "memory");
            asm volatile("cp.async.wait_group 1;" ::: "memory");
        } else {
            asm volatile("cp.async.wait_group 0;" ::: "memory");
        }
        __syncthreads();

        uint32_t ahBase = sb + (i & 1) * GST;
        uint32_t alBase = ahBase + 16384;
        uint32_t bBase  = ahBase + 32768;
#pragma unroll
        for (int ks = 0; ks < 4; ++ks) {
            uint32_t bf[2][4];
#pragma unroll
            for (int in2 = 0; in2 < 2; ++in2)
                ldmatrix_x4(bf[in2], bBase + SWZ128((uint32_t)(
                    (wn * 32 + in2 * 16 + lrow) * 128 + ks * 32 + lcol)));
            uint32_t af[4][4];
            // hi set
#pragma unroll
            for (int im = 0; im < 4; ++im)
                ldmatrix_x4(af[im], ahBase + SWZ128((uint32_t)(
                    (wm * 64 + im * 16 + lrow) * 128 + ks * 32 + lcol)));
#pragma unroll
            for (int im = 0; im < 4; ++im)
#pragma unroll
                for (int in = 0; in < 4; ++in) {
                    uint32_t b0 = bf[in >> 1][in & 1];
                    uint32_t b1 = bf[in >> 1][2 + (in & 1)];
                    mma_f16(acc[im][in], af[im], b0, b1);
                }
            // lo set (reuse af registers)
#pragma unroll
            for (int im = 0; im < 4; ++im)
                ldmatrix_x4(af[im], alBase + SWZ128((uint32_t)(
                    (wm * 64 + im * 16 + lrow) * 128 + ks * 32 + lcol)));
#pragma unroll
            for (int im = 0; im < 4; ++im)
#pragma unroll
                for (int in = 0; in < 4; ++in) {
                    uint32_t b0 = bf[in >> 1][in & 1];
                    uint32_t b1 = bf[in >> 1][2 + (in & 1)];
                    mma_f16(acc[im][in], af[im], b0, b1);
                }
        }
        __syncthreads();
    }

    // epilogue
#pragma unroll
    for (int im = 0; im < 4; ++im) {
        int m  = m0 + wm * 64 + im * 16 + (lane >> 2);
        int r0 = permC ? swap66(m)     : m;
        int r1 = permC ? swap66(m + 8) : (m + 8);
#pragma unroll
        for (int in = 0; in < 4; ++in) {
            int n = n0 + wn * 32 + in * 8 + (lane & 3) * 2;
            if (n >= N) continue;
            float2 v0 = make_float2(acc[im][in][0], acc[im][in][1]);
            float2 v1 = make_float2(acc[im][in][2], acc[im][in][3]);
            if (dsplit) {
                __half h0, l0, h1, l1;
                split2h(v0.x, h0, l0); split2h(v0.y, h1, l1);
                *(__half2*)(dsplit + (size_t)r0 * 2048 + col0 + n) =
                    __halves2half2(h0, h1);
                *(__half2*)(dsplit + (size_t)r0 * 2048 + 1024 + col0 + n) =
                    __halves2half2(l0, l1);
                split2h(v1.x, h0, l0); split2h(v1.y, h1, l1);
                *(__half2*)(dsplit + (size_t)r1 * 2048 + col0 + n) =
                    __halves2half2(h0, h1);
                *(__half2*)(dsplit + (size_t)r1 * 2048 + 1024 + col0 + n) =
                    __halves2half2(l0, l1);
            } else {
                if (bias) {
                    float b0 = bias[n], b1 = bias[n + 1];
                    v0.x += b0; v0.y += b1;
                    v1.x += b0; v1.y += b1;
                }
                *(float2*)(Cz + (size_t)r0 * ldc + col0 + n) = v0;
                *(float2*)(Cz + (size_t)r1 * ldc + col0 + n) = v1;
            }
        }
    }
}

// ---------------------------------------------------------------------------
// Activation split (x -> hi|lo fp16)
// ---------------------------------------------------------------------------
__global__ void split_act_h_kernel(const float* __restrict__ A, __half* __restrict__ out)
{
    size_t idx = (size_t)blockIdx.x * blockDim.x + threadIdx.x;
    if (idx >= (size_t)NTOK * 256) return;
    int m = (int)(idx >> 8), kp = (int)(idx & 255);
    float2 a = *(const float2*)(A + ((size_t)m << 9) + kp * 2);
    __half h0, l0, h1, l1;
    split2h(a.x, h0, l0); split2h(a.y, h1, l1);
    size_t base = (size_t)m * 1024 + kp * 2;
    *(__half2*)(out + base)       = __halves2half2(h0, h1);
    *(__half2*)(out + base + 512) = __halves2half2(l0, l1);
}

// ---------------------------------------------------------------------------
// Unified weight prep: grid.y segments
//  0/1: in_w h/v  (K=512,  N=D_IN_PROJ pad NPAD_IN) -> win
//  2/3: out_w h/v (K=1024, N=512)                   -> wout
//  4:   fc effective (pre-summed) fp16              -> wfc
// ---------------------------------------------------------------------------
__global__ void prep_w_kernel(const float* __restrict__ hin, const float* __restrict__ vin,
                              const float* __restrict__ hout, const float* __restrict__ vout,
                              const float* __restrict__ fcw,
                              __half* __restrict__ win, __half* __restrict__ wout,
                              __half* __restrict__ wfc)
{
    const int seg = blockIdx.y;
    size_t idx = (size_t)blockIdx.x * blockDim.x + threadIdx.x;
    if (seg < 2) {
        if (idx >= ((size_t)NPAD_IN * 512) >> 1) return;
        const float* W = seg ? vin : hin;
        __half* o = win + (size_t)seg * WINSZ;
        int n = (int)(idx >> 8), kp = (int)(idx & 255);
        float2 w = (n < D_IN_PROJ) ? *(const float2*)(W + (size_t)n * 512 + kp * 2)
                                   : make_float2(0.f, 0.f);
        *(__half2*)(o + (size_t)n * 512 + kp * 2) =
            __halves2half2(__float2half_rn(w.x), __float2half_rn(w.y));
    } else if (seg < 4) {
        if (idx >= ((size_t)512 * 1024) >> 1) return;
        const float* W = (seg == 3) ? vout : hout;
        __half* o = wout + (size_t)(seg - 2) * WOUTSZ;
        int n = (int)(idx >> 9), kp = (int)(idx & 511);
        float2 w = *(const float2*)(W + (size_t)n * 1024 + kp * 2);
        *(__half2*)(o + (size_t)n * 1024 + kp * 2) =
            __halves2half2(__float2half_rn(w.x), __float2half_rn(w.y));
    } else {
        if (idx >= (size_t)(D_MODEL * D_INNER) >> 1) return;
        int o = (int)(idx >> 9);
        int j = (int)(idx & 511) * 2;
        float v0, v1;
        if (j < 512) {
            v0 = fcw[(size_t)o * 2048 + j]     + fcw[(size_t)o * 2048 + 512 + j];
            v1 = fcw[(size_t)o * 2048 + j + 1] + fcw[(size_t)o * 2048 + 512 + j + 1];
        } else {
            int jj = j - 512;
            v0 = fcw[(size_t)o * 2048 + 1024 + jj]     + fcw[(size_t)o * 2048 + 1536 + jj];
            v1 = fcw[(size_t)o * 2048 + 1024 + jj + 1] + fcw[(size_t)o * 2048 + 1536 + jj + 1];
        }
        *(__half2*)(wfc + (size_t)o * 1024 + j) =
            __halves2half2(__float2half_rn(v0), __float2half_rn(v1));
    }
}

// ---------------------------------------------------------------------------
// Depthwise causal conv (width 4) + SiLU; batched over dirs
// ---------------------------------------------------------------------------
#define C4N (CONV_DIM / 4)
__global__ void conv_silu_kernel(const float* __restrict__ zxAll,
                                 const float* __restrict__ cw0, const float* __restrict__ cw1,
                                 const float* __restrict__ cb0, const float* __restrict__ cb1,
                                 float* __restrict__ xbcAll)
{
    int idx = blockIdx.x * blockDim.x + threadIdx.x;
    if (idx >= NSEQ * 4 * C4N) return;
    const int z = blockIdx.y;
    const float* zx  = zxAll + (size_t)z * ZXSZ;
    const float* cw  = z ? cw1 : cw0;
    const float* cb  = z ? cb1 : cb0;
    float* xbc = xbcAll + (size_t)z * XBCSZ;

    int c4  = idx % C4N;
    int tmp = idx / C4N;
    int tc  = tmp & 3;
    int seq = tmp >> 2;
    int c   = c4 * 4;
    int t0  = tc * 16;

    float4 w[4];
#pragma unroll
    for (int j = 0; j < 4; ++j) w[j] = *(const float4*)(cw + (c + j) * 4);
    float4 b = *(const float4*)(cb + c);

    size_t ibase = (size_t)seq * LSEQ * D_IN_PROJ + D_INNER + c;
    size_t obase = (size_t)seq * LSEQ * CONV_DIM + c;

    float4 zero = make_float4(0.f, 0.f, 0.f, 0.f);
    float4 x0, x1, x2;
    if (t0 == 0) { x0 = zero; x1 = zero; x2 = zero; }
    else {
        x0 = *(const float4*)(zx + ibase + (size_t)(t0 - 3) * D_IN_PROJ);
        x1 = *(const float4*)(zx + ibase + (size_t)(t0 - 2) * D_IN_PROJ);
        x2 = *(const float4*)(zx + ibase + (size_t)(t0 - 1) * D_IN_PROJ);
    }
#pragma unroll
    for (int t = 0; t < 16; ++t) {
        float4 xt = *(const float4*)(zx + ibase + (size_t)(t0 + t) * D_IN_PROJ);
        float4 v;
        v.x = fmaf(x0.x, w[0].x, fmaf(x1.x, w[0].y, fmaf(x2.x, w[0].z, fmaf(xt.x, w[0].w, b.x))));
        v.y = fmaf(x0.y, w[1].x, fmaf(x1.y, w[1].y, fmaf(x2.y, w[1].z, fmaf(xt.y, w[1].w, b.y))));
        v.z = fmaf(x0.z, w[2].x, fmaf(x1.z, w[2].y, fmaf(x2.z, w[2].z, fmaf(xt.z, w[2].w, b.z))));
        v.w = fmaf(x0.w, w[3].x, fmaf(x1.w, w[3].y, fmaf(x2.w, w[3].z, fmaf(xt.w, w[3].w, b.w))));
        v.x = fsilu(v.x);
        v.y = fsilu(v.y);
        v.z = fsilu(v.z);
        v.w = fsilu(v.w);
        *(float4*)(xbc + obase + (size_t)(t0 + t) * CONV_DIM) = v;
        x0 = x1; x1 = x2; x2 = xt;
    }
}

// ---------------------------------------------------------------------------
// G kernel: block per (seq, dir). G[t][s] = C[t].B[s]
// ---------------------------------------------------------------------------
#define GK_BCS 132
#define GK_BTS 68
#define GK_SMEM ((64 * GK_BCS + 128 * GK_BTS) * 4)

__global__ __launch_bounds__(256)
void gmat_kernel(const float* __restrict__ xbcAll, float* __restrict__ GAll)
{
    extern __shared__ float sm[];
    float* Cs = sm;
    float* Bt = Cs + 64 * GK_BCS;

    const int seq = blockIdx.x;
    const int z   = blockIdx.y;
    const int tid = threadIdx.x;
    const float* xbc = xbcAll + (size_t)z * XBCSZ;

    for (int i = tid; i < 64 * 128; i += 256) {
        int t = i >> 7, n = i & 127;
        size_t base = (size_t)(seq * LSEQ + t) * CONV_DIM;
        Bt[n * GK_BTS + t] = xbc[base + D_INNER + n];
        Cs[t * GK_BCS + n] = xbc[base + D_INNER + D_STATE + n];
    }
    __syncthreads();

    const int tt = (tid >> 4) << 2;
    const int ss = (tid & 15) << 2;

    float wa[4][4];
#pragma unroll
    for (int i = 0; i < 4; ++i)
#pragma unroll
        for (int j = 0; j < 4; ++j) wa[i][j] = 0.f;

    if (ss <= tt + 3) {
        for (int n = 0; n < 128; n += 4) {
            float4 cr[4], bt[4];
#pragma unroll
            for (int i = 0; i < 4; ++i) cr[i] = *(const float4*)&Cs[(tt + i) * GK_BCS + n];
#pragma unroll
            for (int k = 0; k < 4; ++k) bt[k] = *(const float4*)&Bt[(n + k) * GK_BTS + ss];
#pragma unroll
            for (int i = 0; i < 4; ++i) {
                wa[i][0] = fmaf(cr[i].x, bt[0].x, wa[i][0]);
                wa[i][1] = fmaf(cr[i].x, bt[0].y, wa[i][1]);
                wa[i][2] = fmaf(cr[i].x, bt[0].z, wa[i][2]);
                wa[i][3] = fmaf(cr[i].x, bt[0].w, wa[i][3]);
                wa[i][0] = fmaf(cr[i].y, bt[1].x, wa[i][0]);
                wa[i][1] = fmaf(cr[i].y, bt[1].y, wa[i][1]);
                wa[i][2] = fmaf(cr[i].y, bt[1].z, wa[i][2]);
                wa[i][3] = fmaf(cr[i].y, bt[1].w, wa[i][3]);
                wa[i][0] = fmaf(cr[i].z, bt[2].x, wa[i][0]);
                wa[i][1] = fmaf(cr[i].z, bt[2].y, wa[i][1]);
                wa[i][2] = fmaf(cr[i].z, bt[2].z, wa[i][2]);
                wa[i][3] = fmaf(cr[i].z, bt[2].w, wa[i][3]);
                wa[i][0] = fmaf(cr[i].w, bt[3].x, wa[i][0]);
                wa[i][1] = fmaf(cr[i].w, bt[3].y, wa[i][1]);
                wa[i][2] = fmaf(cr[i].w, bt[3].z, wa[i][2]);
                wa[i][3] = fmaf(cr[i].w, bt[3].w, wa[i][3]);
            }
        }
    }
    float* gp = GAll + (size_t)z * GSZ + (size_t)seq * 4096;
#pragma unroll
    for (int i = 0; i < 4; ++i)
        *(float4*)&gp[(tt + i) * 64 + ss] =
            make_float4(wa[i][0], wa[i][1], wa[i][2], wa[i][3]);
}

// ---------------------------------------------------------------------------
// SSM phase-2: block per (seq*head, dir). Balanced row-pair assignment.
// ---------------------------------------------------------------------------
#define S2S 68

__global__ __launch_bounds__(256)
void ssm2_kernel(const float* __restrict__ zxAll, const float* __restrict__ xbcAll,
                 const float* __restrict__ GAll,
                 const float* __restrict__ A0, const float* __restrict__ A1,
                 const float* __restrict__ db0, const float* __restrict__ db1,
                 const float* __restrict__ Dp0, const float* __restrict__ Dp1,
                 float* __restrict__ yAll)
{
    __shared__ float Wts[64 * S2S];
    __shared__ float xs [64 * S2S];
    __shared__ float dts[64];
    __shared__ float css[64];

    const int z   = blockIdx.y;
    const int seq = blockIdx.x >> 4;
    const int h   = blockIdx.x & 15;
    const int tid = threadIdx.x;

    const float* zx  = zxAll  + (size_t)z * ZXSZ;
    const float* xbc = xbcAll + (size_t)z * XBCSZ;
    const float* G   = GAll   + (size_t)z * GSZ;
    const float* A_log   = z ? A1  : A0;
    const float* dt_bias = z ? db1 : db0;
    const float* Dp      = z ? Dp1 : Dp0;
    float* y = yAll + (size_t)z * YSZ;

    for (int i = tid; i < 64 * 64; i += 256) {
        int t = i >> 6, p = i & 63;
        xs[t * S2S + p] = xbc[(size_t)(seq * LSEQ + t) * CONV_DIM + h * HEADDIM + p];
    }
    if (tid < 64) {
        float raw = zx[(size_t)(seq * LSEQ + tid) * D_IN_PROJ + (D_INNER + CONV_DIM) + h]
                    + dt_bias[h];
        dts[tid] = (raw > 20.f) ? raw : log1pf(__expf(raw));
    }
    __syncthreads();
    if (tid == 0) {
        float a = -__expf(A_log[h]);
        float run = 0.f;
        for (int t = 0; t < 64; ++t) { run += dts[t] * a; css[t] = run; }
    }
    __syncthreads();

    const float* gp = G + (size_t)seq * 4096;
    for (int i = tid; i < 1024; i += 256) {
        int t  = i >> 4;
        int s4 = (i & 15) << 2;
        float4 g = *(const float4*)&gp[t * 64 + s4];
        float4 wv;
        wv.x = (s4 + 0 <= t) ? g.x * __expf(css[t] - css[s4 + 0]) * dts[s4 + 0] : 0.f;
        wv.y = (s4 + 1 <= t) ? g.y * __expf(css[t] - css[s4 + 1]) * dts[s4 + 1] : 0.f;
        wv.z = (s4 + 2 <= t) ? g.z * __expf(css[t] - css[s4 + 2]) * dts[s4 + 2] : 0.f;
        wv.w = (s4 + 3 <= t) ? g.w * __expf(css[t] - css[s4 + 3]) * dts[s4 + 3] : 0.f;
        *(float4*)&Wts[t * S2S + s4] = wv;
    }
    __syncthreads();

    const int tb = tid >> 4;
    const int ss = (tid & 15) << 2;
    const float dcoef = Dp[h];

#pragma unroll
    for (int pr = 0; pr < 2; ++pr) {
        const int r0 = pr ? (62 - 2 * tb) : (2 * tb);
        const int hiB = r0 + 1;
        float ya[2][4];
#pragma unroll
        for (int i = 0; i < 2; ++i) {
            float4 xv = *(const float4*)&xs[(r0 + i) * S2S + ss];
            ya[i][0] = dcoef * xv.x; ya[i][1] = dcoef * xv.y;
            ya[i][2] = dcoef * xv.z; ya[i][3] = dcoef * xv.w;
        }
        for (int s0 = 0; s0 <= hiB; s0 += 4) {
            float4 wr[2], xr[4];
#pragma unroll
            for (int i = 0; i < 2; ++i) wr[i] = *(const float4*)&Wts[(r0 + i) * S2S + s0];
#pragma unroll
            for (int k = 0; k < 4; ++k) xr[k] = *(const float4*)&xs[(s0 + k) * S2S + ss];
#pragma unroll
            for (int i = 0; i < 2; ++i) {
                ya[i][0] = fmaf(wr[i].x, xr[0].x, ya[i][0]);
                ya[i][1] = fmaf(wr[i].x, xr[0].y, ya[i][1]);
                ya[i][2] = fmaf(wr[i].x, xr[0].z, ya[i][2]);
                ya[i][3] = fmaf(wr[i].x, xr[0].w, ya[i][3]);
                ya[i][0] = fmaf(wr[i].y, xr[1].x, ya[i][0]);
                ya[i][1] = fmaf(wr[i].y, xr[1].y, ya[i][1]);
                ya[i][2] = fmaf(wr[i].y, xr[1].z, ya[i][2]);
                ya[i][3] = fmaf(wr[i].y, xr[1].w, ya[i][3]);
                ya[i][0] = fmaf(wr[i].z, xr[2].x, ya[i][0]);
                ya[i][1] = fmaf(wr[i].z, xr[2].y, ya[i][1]);
                ya[i][2] = fmaf(wr[i].z, xr[2].z, ya[i][2]);
                ya[i][3] = fmaf(wr[i].z, xr[2].w, ya[i][3]);
                ya[i][0] = fmaf(wr[i].w, xr[3].x, ya[i][0]);
                ya[i][1] = fmaf(wr[i].w, xr[3].y, ya[i][1]);
                ya[i][2] = fmaf(wr[i].w, xr[3].z, ya[i][2]);
                ya[i][3] = fmaf(wr[i].w, xr[3].w, ya[i][3]);
            }
        }
#pragma unroll
        for (int i = 0; i < 2; ++i) {
            float4 v = make_float4(ya[i][0], ya[i][1], ya[i][2], ya[i][3]);
            *(float4*)&y[(size_t)(seq * LSEQ + r0 + i) * D_INNER + h * HEADDIM + ss] = v;
        }
    }
}

// ---------------------------------------------------------------------------
// Gated RMSNorm + fp16 split emit; batched over dirs. Vectorized float4/half2.
// ---------------------------------------------------------------------------
__global__ __launch_bounds__(256)
void gate_norm_split_kernel(const float* __restrict__ zxAll,
                            const float* __restrict__ nw0, const float* __restrict__ nw1,
                            const float* __restrict__ yAll, __half* __restrict__ outAll)
{
    const int row = blockIdx.x;
    const int z   = blockIdx.y;
    const int tid = threadIdx.x;
    __shared__ float wsum[8];

    const float* zx = zxAll + (size_t)z * ZXSZ;
    const float* y  = yAll  + (size_t)z * YSZ;
    const float* norm_w = z ? nw1 : nw0;
    __half* out = outAll + (size_t)z * ASZ;

    const int c = tid * 4;
    float4 zz = *(const float4*)(zx + (size_t)row * D_IN_PROJ + c);
    float4 yv = *(const float4*)(y  + (size_t)row * D_INNER   + c);
    float4 g;
    g.x = yv.x * fsilu(zz.x);
    g.y = yv.y * fsilu(zz.y);
    g.z = yv.z * fsilu(zz.z);
    g.w = yv.w * fsilu(zz.w);
    float ss = g.x * g.x + g.y * g.y + g.z * g.z + g.w * g.w;
#pragma unroll
    for (int off = 16; off; off >>= 1)
        ss += __shfl_xor_sync(0xffffffffu, ss, off);
    if ((tid & 31) == 0) wsum[tid >> 5] = ss;
    __syncthreads();
    float tot = wsum[0] + wsum[1] + wsum[2] + wsum[3]
              + wsum[4] + wsum[5] + wsum[6] + wsum[7];
    float scale = rsqrtf(tot / (float)D_INNER + EPS);

    float4 nw = *(const float4*)(norm_w + c);
    float o0 = g.x * scale * nw.x;
    float o1 = g.y * scale * nw.y;
    float o2 = g.z * scale * nw.z;
    float o3 = g.w * scale * nw.w;
    __half h0, l0, h1, l1, h2, l2, h3, l3;
    split2h(o0, h0, l0); split2h(o1, h1, l1);
    split2h(o2, h2, l2); split2h(o3, h3, l3);
    size_t base = (size_t)row * 2048 + c;
    *(__half2*)(out + base)            = __halves2half2(h0, h1);
    *(__half2*)(out + base + 2)        = __halves2half2(h2, h3);
    *(__half2*)(out + base + 1024)     = __halves2half2(l0, l1);
    *(__half2*)(out + base + 1024 + 2) = __halves2half2(l2, l3);
}

// ---------------------------------------------------------------------------
// Host side
// ---------------------------------------------------------------------------
extern "C" void kernel_launch(void* const* d_in, const int* in_sizes, int n_in,
                              void* d_out, int out_size)
{
    (void)in_sizes; (void)n_in; (void)out_size;
    const float* x        = (const float*)d_in[0];
    const float* h_in_w   = (const float*)d_in[1];
    const float* h_conv_w = (const float*)d_in[2];
    const float* h_conv_b = (const float*)d_in[3];
    const float* h_A_log  = (const float*)d_in[4];
    const float* h_dt_b   = (const float*)d_in[5];
    const float* h_D      = (const float*)d_in[6];
    const float* h_norm_w = (const float*)d_in[7];
    const float* h_out_w  = (const float*)d_in[8];
    const float* v_in_w   = (const float*)d_in[9];
    const float* v_conv_w = (const float*)d_in[10];
    const float* v_conv_b = (const float*)d_in[11];
    const float* v_A_log  = (const float*)d_in[12];
    const float* v_dt_b   = (const float*)d_in[13];
    const float* v_D      = (const float*)d_in[14];
    const float* v_norm_w = (const float*)d_in[15];
    const float* v_out_w  = (const float*)d_in[16];
    const float* fc_w     = (const float*)d_in[17];
    const float* fc_b     = (const float*)d_in[18];
    float* out = (float*)d_out;

    float *zx, *xbc, *y, *G;
    __half *xsplit, *asplitA, *asplitB, *win, *wout, *wfc;
    cudaGetSymbolAddress((void**)&zx,      g_zx);
    cudaGetSymbolAddress((void**)&xbc,     g_xbc);
    cudaGetSymbolAddress((void**)&y,       g_y);
    cudaGetSymbolAddress((void**)&G,       g_G);
    cudaGetSymbolAddress((void**)&xsplit,  g_xsplit);
    cudaGetSymbolAddress((void**)&asplitA, g_asplitA);
    cudaGetSymbolAddress((void**)&asplitB, g_asplitB);
    cudaGetSymbolAddress((void**)&win,     g_win);
    cudaGetSymbolAddress((void**)&wout,    g_wout);
    cudaGetSymbolAddress((void**)&wfc,     g_wfc);

    cudaFuncSetAttribute(gmat_kernel, cudaFuncAttributeMaxDynamicSharedMemorySize,
                         GK_SMEM);
    cudaFuncSetAttribute(gemm_tc_kernel, cudaFuncAttributeMaxDynamicSharedMemorySize,
                         GSM_TOTAL);

    const int TPB = 256;

    // weight prep: one launch (5 segments), activation split: one launch
    {
        dim3 g((((size_t)NPAD_IN * 512 / 2) + TPB - 1) / TPB, 5);
        prep_w_kernel<<<g, TPB>>>(h_in_w, v_in_w, h_out_w, v_out_w, fc_w,
                                  win, wout, wfc);
    }
    split_act_h_kernel<<<(NTOK * 256 + TPB - 1) / TPB, TPB>>>(x, xsplit);

    // in-proj (both dirs)
    {
        dim3 g(NPAD_IN / 128, NTOK / 128, 2);
        gemm_tc_kernel<<<g, 256, GSM_TOTAL>>>(xsplit, 0, win, win + WINSZ,
                                              zx, ZXSZ, nullptr,
                                              512, D_IN_PROJ, D_IN_PROJ, 0, 0,
                                              nullptr, 1, 0);
    }
    {
        dim3 g((NSEQ * 4 * C4N + TPB - 1) / TPB, 2);
        conv_silu_kernel<<<g, TPB>>>(zx, h_conv_w, v_conv_w, h_conv_b, v_conv_b, xbc);
    }
    {
        dim3 g(NSEQ, 2);
        gmat_kernel<<<g, 256, GK_SMEM>>>(xbc, G);
    }
    {
        dim3 g(NSEQ * NHEADS, 2);
        ssm2_kernel<<<g, 256>>>(zx, xbc, G, h_A_log, v_A_log,
                                h_dt_b, v_dt_b, h_D, v_D, y);
    }
    {
        dim3 g(NTOK, 2);
        gate_norm_split_kernel<<<g, 256>>>(zx, h_norm_w, v_norm_w, y, asplitA);
    }
    // out-proj (both dirs)
    {
        dim3 g(512 / 128, NTOK / 128, 2);
        gemm_tc_kernel<<<g, 256, GSM_TOTAL>>>(asplitA, ASZ, wout, wout + WOUTSZ,
                                              nullptr, 0, asplitB,
                                              1024, 512, 0, 512, 0,
                                              nullptr, 0, 1);
    }
    // final fc
    {
        dim3 g(512 / 128, NTOK / 128, 1);
        gemm_tc_kernel<<<g, 256, GSM_TOTAL>>>(asplitB, 0, wfc, nullptr,
                                              out, 0, nullptr,
                                              1024, 512, 512, 0, 0, fc_b, 0, 0);
    }
}